// round 16
// baseline (speedup 1.0000x reference)
#include <cuda_runtime.h>
#include <cuda_bf16.h>
#include <cstdint>

// VoxelPooler: bin points into per-(quarter-row, y%4-class) sub-lists in ONE
// pass, then a lean rowpool (128 threads, 16 CTAs/SM): warp w consumes its
// own pre-grouped class list, coalesced feature loads (one point per warp-op,
// lanes = channels), race-free smem accumulate, structured readout.
//
// Tile: Y-MAJOR, stride 65: acc[yl*65 + c]   (quarter-row: 50 y, 13 KB)
//   accumulate: lane l, fixed y -> bank (y+l)%32    conflict-free
//   readout:    fixed c, y=32j+l -> bank (l+c)%32   conflict-free, STG coalesced
//
// geometry [B,N,D,H,W,3] f32, features [B,N,D,H,W,64] f32
// output   [B, Z*C, X, Y] f32, Z=8 C=64 X=200 Y=200

constexpr int GX = 200;
constexpr int GY = 200;
constexpr int GZ = 8;
constexpr int CH = 64;
constexpr int XY = GX * GY;
constexpr int NB = 4;
constexpr int PPB   = 6 * 41 * 16 * 44;    // 173184
constexpr int PTOT  = NB * PPB;            // 692736
constexpr int SEGY  = 50;                  // y-span per segment
constexpr int NSEG  = NB * GZ * GX * 4;    // 25600 quarter-row segments
constexpr int NCLS  = NSEG * 4;            // 102400 class lists (y%4)
constexpr int PADC  = CH + 1;              // 65
constexpr int CAPC  = 32;                  // slots/class; occupancy ~Poisson(4.5)
constexpr int QP    = PTOT / 4;            // 173184 points per unroll chunk

__device__ int      d_count[NCLS];                  // zero-init; re-zeroed by rowpool
__device__ unsigned d_plist[(size_t)NCLS * CAPC];   // (p<<8)|y_local  (13.1 MB)

__global__ void __launch_bounds__(256) vp_bin_fill(
    const float* __restrict__ geo,
    const float* __restrict__ vsize,
    const float* __restrict__ vorig)
{
    int t = blockIdx.x * blockDim.x + threadIdx.x;
    if (t >= QP) return;                   // grid overshoot guard (R11 bug fix:
                                           // surplus threads double-counted points)

    float ox = __ldg(&vorig[0]), oy = __ldg(&vorig[1]), oz = __ldg(&vorig[2]);
    float sx = __ldg(&vsize[0]), sy = __ldg(&vsize[1]), sz = __ldg(&vsize[2]);

    #pragma unroll
    for (int k = 0; k < 4; ++k) {              // 4 points/thread, indep chains
        int p = t + k * QP;                    // p < PTOT guaranteed: t < QP

        const float* g = geo + (size_t)p * 3;
        float px = g[0], py = g[1], pz = g[2];

        // fp32 semantics matching jnp: sub(rn), div(rn), floorf, int cast
        int ix = (int)floorf(__fdiv_rn(px - ox, sx));
        int iy = (int)floorf(__fdiv_rn(py - oy, sy));
        int iz = (int)floorf(__fdiv_rn(pz - oz, sz));

        if ((unsigned)ix >= (unsigned)GX ||
            (unsigned)iy >= (unsigned)GY ||
            (unsigned)iz >= (unsigned)GZ) continue;   // ref scatters zeros: no-op

        int b   = p / PPB;
        int yq  = iy / SEGY;                          // 0..3
        int yl  = iy - yq * SEGY;                     // 0..49
        int cl  = ((((b * GZ + iz) * GX + ix) << 2) + yq) * 4 + (yl & 3);
        int pos = atomicAdd(&d_count[cl], 1);
        if (pos < CAPC)
            d_plist[(size_t)cl * CAPC + pos] = ((unsigned)p << 8) | (unsigned)yl;
    }
}

// One CTA (128 threads) per quarter-row segment; warp w consumes class list w.
__global__ void __launch_bounds__(128) vp_rowpool(
    const float* __restrict__ feat,
    float* __restrict__ out)
{
    __shared__ float acc[3252];           // 50*65 = 3250 words (+2 round to /4)

    int r = blockIdx.x;
    int tid = threadIdx.x, warp = tid >> 5, lane = tid & 31;
    int cl = (r << 2) + warp;

    // issue list-count + entry loads early (consumed after the barrier)
    int nw = d_count[cl];                 // per-warp broadcast load
    if (nw > CAPC) nw = CAPC;
    unsigned e = 0;
    if (lane < nw) e = d_plist[(size_t)cl * CAPC + lane];   // coalesced
    if (lane == 0) d_count[cl] = 0;       // reset for next graph replay

    // zero tile (float4)
    float4* accv = reinterpret_cast<float4*>(acc);
    #pragma unroll
    for (int i = tid; i < 3252 / 4; i += 128)
        accv[i] = make_float4(0.f, 0.f, 0.f, 0.f);
    __syncthreads();

    // accumulate: entries live in lane registers, broadcast via shfl.
    // one point per warp-op -> feature LDG coalesced (2 x 128B lines).
    int j = 0;
    for (; j + 1 < nw; j += 2) {
        unsigned ea = __shfl_sync(~0u, e, j);
        unsigned eb = __shfl_sync(~0u, e, j + 1);
        const float* fa = feat + (size_t)(ea >> 8) * CH;
        const float* fb = feat + (size_t)(eb >> 8) * CH;
        float a0 = fa[lane], a1 = fa[lane + 32];
        float b0 = fb[lane], b1 = fb[lane + 32];
        int ya = (int)(ea & 255u) * PADC;
        int yb = (int)(eb & 255u) * PADC;
        acc[ya + lane]      += a0;        // bank (y+l)%32: conflict-free
        acc[ya + lane + 32] += a1;
        acc[yb + lane]      += b0;
        acc[yb + lane + 32] += b1;
    }
    if (j < nw) {
        unsigned ea = __shfl_sync(~0u, e, j);
        const float* fa = feat + (size_t)(ea >> 8) * CH;
        float a0 = fa[lane], a1 = fa[lane + 32];
        int ya = (int)(ea & 255u) * PADC;
        acc[ya + lane]      += a0;
        acc[ya + lane + 32] += a1;
    }
    __syncthreads();

    // readout: warp w owns channels 16w..16w+15; lane strides y by 32.
    // LDS bank (l+c)%32 conflict-free; STG.32 coalesced; no divisions.
    int row = r >> 2;
    int ybase = (r & 3) * SEGY;
    int b  = row / (GZ * GX);
    int zx = row % (GZ * GX);
    int z = zx / GX, x = zx % GX;
    float* ob = out + ((size_t)(b * GZ + z) * CH) * XY + (size_t)x * GY + ybase;

    #pragma unroll
    for (int ci = 0; ci < 16; ++ci) {
        int c = (warp << 4) + ci;
        const float* arow = acc + c;
        float* orow = ob + (size_t)c * XY;
        orow[lane] = arow[(size_t)lane * PADC];        // y = 0..31
        if (lane < SEGY - 32) {                        // y = 32..49
            int yl = 32 + lane;
            orow[yl] = arow[(size_t)yl * PADC];
        }
    }
}

extern "C" void kernel_launch(void* const* d_in, const int* in_sizes, int n_in,
                              void* d_out, int out_size)
{
    const float* geo   = (const float*)d_in[0];
    const float* feat  = (const float*)d_in[1];
    const float* vsize = (const float*)d_in[2];
    const float* vorig = (const float*)d_in[3];
    float* out = (float*)d_out;

    vp_bin_fill<<<(QP + 255) / 256, 256>>>(geo, vsize, vorig);
    vp_rowpool<<<NSEG, 128>>>(feat, out);
}